// round 1
// baseline (speedup 1.0000x reference)
#include <cuda_runtime.h>

#define NL 32
#define DM 1024
#define NK 4
#define IQO 1024
#define IKV 256
#define IFF 2816

// Output row layout: row = (l*7 + mod)*8 + s*4 + k, columns = DM.
// MODULE_ORDER = [q, k, v, gate, up, o, down] -> mod 0..6.

__device__ __forceinline__ float dot4(float4 a, float4 b, float acc) {
    acc = fmaf(a.x, b.x, acc);
    acc = fmaf(a.y, b.y, acc);
    acc = fmaf(a.z, b.z, acc);
    acc = fmaf(a.w, b.w, acc);
    return acc;
}

__device__ __forceinline__ float wsum(float v) {
    v += __shfl_xor_sync(0xffffffffu, v, 16);
    v += __shfl_xor_sync(0xffffffffu, v, 8);
    v += __shfl_xor_sync(0xffffffffu, v, 4);
    v += __shfl_xor_sync(0xffffffffu, v, 2);
    v += __shfl_xor_sync(0xffffffffu, v, 1);
    return v;
}

// ---- Affine module (q/k/v/o): proj[k,d] = sum_i x[k,i] * W[d,i], K=4 RHS ----
template <int I>
__device__ void affine_block(const float* __restrict__ xg,
                             const float* __restrict__ W,
                             float* __restrict__ out,
                             int l, int dt, int mod,
                             float4* xs4, int tid, int lane, int wid)
{
    // Stage x[4][I] into smem: 4*I floats = I float4.
    const float4* xg4 = reinterpret_cast<const float4*>(xg) + (size_t)l * I; // l*4*I floats / 4
    #pragma unroll
    for (int i = tid; i < I; i += 256) xs4[i] = xg4[i];
    __syncthreads();

    const int d0 = dt * 32 + wid * 4;
    const float4* w4 = reinterpret_cast<const float4*>(W) + ((size_t)l * DM + d0) * (I / 4);

    float acc[4][4];
    #pragma unroll
    for (int r = 0; r < 4; r++)
        #pragma unroll
        for (int k = 0; k < 4; k++) acc[r][k] = 0.f;

    #pragma unroll 2
    for (int c = lane; c < I / 4; c += 32) {
        float4 x0 = xs4[c];
        float4 x1 = xs4[(I / 4) + c];
        float4 x2 = xs4[2 * (I / 4) + c];
        float4 x3 = xs4[3 * (I / 4) + c];
        #pragma unroll
        for (int r = 0; r < 4; r++) {
            float4 w = __ldcs(w4 + r * (I / 4) + c);
            acc[r][0] = dot4(w, x0, acc[r][0]);
            acc[r][1] = dot4(w, x1, acc[r][1]);
            acc[r][2] = dot4(w, x2, acc[r][2]);
            acc[r][3] = dot4(w, x3, acc[r][3]);
        }
    }

    const int rowb = (l * 7 + mod) * 8 + 4;
    #pragma unroll
    for (int r = 0; r < 4; r++)
        #pragma unroll
        for (int k = 0; k < 4; k++) {
            float v = wsum(acc[r][k]);
            if (lane == (r * 4 + k)) out[(size_t)(rowb + k) * DM + d0 + r] = v;
        }
}

// ---- MLP module: 3 modules (gate/up/down) share W_down -> 12 accumulators ----
__device__ void mlp_block(const float* __restrict__ cm,
                          const float* __restrict__ Wd,
                          float* __restrict__ out,
                          int l, int dt,
                          float4* xs4, int tid, int lane, int wid)
{
    const int d0 = dt * 32 + wid * 4;
    const float4* xg4 = reinterpret_cast<const float4*>(cm) + (size_t)l * 3 * NK * (IFF / 4);
    const float4* w4  = reinterpret_cast<const float4*>(Wd) + ((size_t)l * DM + d0) * (IFF / 4);

    float acc[4][12];
    #pragma unroll
    for (int r = 0; r < 4; r++)
        #pragma unroll
        for (int j = 0; j < 12; j++) acc[r][j] = 0.f;

    // Staging: 12 rows x 256 floats per chunk = 768 float4; thread t stages
    // rows j0, j0+4, j0+8 at column i0.
    const int j0 = tid >> 6;
    const int i0 = tid & 63;
    const int base = j0 * (IFF / 4) + i0;

    float4 pre0 = xg4[base];
    float4 pre1 = xg4[base + 4 * (IFF / 4)];
    float4 pre2 = xg4[base + 8 * (IFF / 4)];

    for (int c = 0; c < 11; ++c) {
        __syncthreads();                 // previous chunk fully consumed
        xs4[tid]       = pre0;
        xs4[tid + 256] = pre1;
        xs4[tid + 512] = pre2;
        __syncthreads();
        if (c < 10) {
            pre0 = xg4[base + (c + 1) * 64];
            pre1 = xg4[base + 4 * (IFF / 4) + (c + 1) * 64];
            pre2 = xg4[base + 8 * (IFF / 4) + (c + 1) * 64];
        }
        #pragma unroll
        for (int it = 0; it < 2; ++it) {
            const int cc = it * 32 + lane;
            const int wc = c * 64 + cc;
            float4 w0 = __ldcs(w4 + 0 * (IFF / 4) + wc);
            float4 w1 = __ldcs(w4 + 1 * (IFF / 4) + wc);
            float4 w2 = __ldcs(w4 + 2 * (IFF / 4) + wc);
            float4 w3 = __ldcs(w4 + 3 * (IFF / 4) + wc);
            #pragma unroll
            for (int j = 0; j < 12; j++) {
                float4 xv = xs4[j * 64 + cc];
                acc[0][j] = dot4(w0, xv, acc[0][j]);
                acc[1][j] = dot4(w1, xv, acc[1][j]);
                acc[2][j] = dot4(w2, xv, acc[2][j]);
                acc[3][j] = dot4(w3, xv, acc[3][j]);
            }
        }
    }

    // j = m*4 + k ; m=0 -> gate (mod 3), m=1 -> up (mod 4), m=2 -> down (mod 6)
    #pragma unroll
    for (int j = 0; j < 12; j++) {
        const int m = j >> 2;
        const int k = j & 3;
        const int mod = (m == 0) ? 3 : (m == 1) ? 4 : 6;
        const int rowb = (l * 7 + mod) * 8 + 4 + k;
        #pragma unroll
        for (int r = 0; r < 4; r++) {
            float v = wsum(acc[r][j]);
            if (lane == ((j * 4 + r) & 31)) out[(size_t)rowb * DM + d0 + r] = v;
        }
    }
}

__global__ __launch_bounds__(256, 2)
void bse_fused_kernel(const float* __restrict__ residual,
                      const float* __restrict__ cq,
                      const float* __restrict__ ck,
                      const float* __restrict__ cv,
                      const float* __restrict__ co,
                      const float* __restrict__ cm,
                      const float* __restrict__ Wq,
                      const float* __restrict__ Wk,
                      const float* __restrict__ Wv,
                      const float* __restrict__ Wo,
                      const float* __restrict__ Wd,
                      float* __restrict__ out)
{
    __shared__ float4 xs4[1024];   // 16 KB: A uses up to 1024 f4; MLP uses 768 f4
    const int bid = blockIdx.x;
    const int tid = threadIdx.x;
    const int lane = tid & 31;
    const int wid = tid >> 5;

    if (bid < 1024) {
        // W_down blocks first (longest-running)
        mlp_block(cm, Wd, out, bid >> 5, bid & 31, xs4, tid, lane, wid);
    } else if (bid < 2048) {
        const int a = bid - 1024;
        affine_block<IQO>(cq, Wq, out, a >> 5, a & 31, 0, xs4, tid, lane, wid);
    } else if (bid < 3072) {
        const int a = bid - 2048;
        affine_block<IQO>(co, Wo, out, a >> 5, a & 31, 5, xs4, tid, lane, wid);
    } else if (bid < 4096) {
        const int a = bid - 3072;
        affine_block<IKV>(ck, Wk, out, a >> 5, a & 31, 1, xs4, tid, lane, wid);
    } else if (bid < 5120) {
        const int a = bid - 4096;
        affine_block<IKV>(cv, Wv, out, a >> 5, a & 31, 2, xs4, tid, lane, wid);
    } else {
        // Residual copy: residual[l,mod,k,:] -> out row (g*8 + k)
        const float4* src = reinterpret_cast<const float4*>(residual);
        float4* dst = reinterpret_cast<float4*>(out);
        const int n = NL * 7 * NK * (DM / 4);          // 229376 float4
        for (int e = (bid - 5120) * 256 + tid; e < n; e += 512 * 256) {
            const int d = e & 255;
            const int k = (e >> 8) & 3;
            const int g = e >> 10;
            dst[(size_t)(g * 8 + k) * 256 + d] = __ldcs(src + e);
        }
    }
}

extern "C" void kernel_launch(void* const* d_in, const int* in_sizes, int n_in,
                              void* d_out, int out_size)
{
    (void)in_sizes; (void)n_in; (void)out_size;
    const float* residual = (const float*)d_in[0];
    const float* cq = (const float*)d_in[1];
    const float* ck = (const float*)d_in[2];
    const float* cv = (const float*)d_in[3];
    const float* co = (const float*)d_in[4];
    const float* cm = (const float*)d_in[5];
    const float* Wq = (const float*)d_in[6];
    const float* Wk = (const float*)d_in[7];
    const float* Wv = (const float*)d_in[8];
    const float* Wo = (const float*)d_in[9];
    const float* Wd = (const float*)d_in[10];
    float* out = (float*)d_out;

    bse_fused_kernel<<<5632, 256>>>(residual, cq, ck, cv, cv ? co : co, cm,
                                    Wq, Wk, Wv, Wo, Wd, out);
}